// round 16
// baseline (speedup 1.0000x reference)
#include <cuda_runtime.h>
#include <cuda_fp16.h>
#include <cstdint>

#define B_SZ 16384
#define F_SZ 9000
#define BK   64
#define NCH  141             // ceil(9000/64); last chunk 40 valid k
#define PLA  2048            // A sub-plane: 64 rows x 32B (k16)
#define PLW  4096            // W sub-plane: 128 rows x 32B (k16)
// stage layout: A_s0..A_s3 [8KB] | W_s0..W_s3 [16KB] = 24KB
#define W_OFF   8192
#define WCHUNK  16384        // W bytes per chunk in g_wh (4 sub-planes)
#define STG_SZ  24576
#define SMEM_DYN (2 * STG_SZ)   // 49152 B -> no attribute needed; occ 3 (reg-capped)

__device__ float g_scratch[B_SZ * 256];
__device__ int g_mode;
__device__ float g_wsum[128];
__device__ unsigned char g_wh[NCH * WCHUNK];   // per-chunk fp16 W sub-planes, SWZ layout

__device__ __forceinline__ float screlu(float x) {
    x = fminf(fmaxf(x, 0.0f), 1.0f);
    return x * x;
}

__device__ __forceinline__ uint32_t smem_u32(const void* p) {
    uint32_t a;
    asm("{ .reg .u64 t; cvta.to.shared.u64 t, %1; cvt.u32.u64 %0, t; }" : "=r"(a) : "l"(p));
    return a;
}

// XOR swizzle for 32B rows: row r, 16B-half h -> conflict-free ldmatrix/STS
#define SWZ(r, h) ((uint32_t)((r) * 32 + (((h) ^ (((r) >> 2) & 1)) << 4)))

__device__ __forceinline__ uint32_t h2u(__half2 h) {
    uint32_t u;
    *(__half2*)&u = h;
    return u;
}
__device__ __forceinline__ uint32_t cvtH2(float x0, float x1) {
    return h2u(__floats2half2_rn(x0, x1));
}

#define LDSM_X4(r, addr)                                                         \
    asm volatile("ldmatrix.sync.aligned.m8n8.x4.shared.b16 {%0,%1,%2,%3}, [%4];" \
                 : "=r"((r)[0]), "=r"((r)[1]), "=r"((r)[2]), "=r"((r)[3])        \
                 : "r"(addr))

#define MMA16816(c, a, bb0, bb1)                                                 \
    asm volatile("mma.sync.aligned.m16n8k16.row.col.f32.f16.f16.f32 "            \
                 "{%0,%1,%2,%3}, {%4,%5,%6,%7}, {%8,%9}, {%0,%1,%2,%3};"         \
                 : "+f"((c)[0]), "+f"((c)[1]), "+f"((c)[2]), "+f"((c)[3])        \
                 : "r"((a)[0]), "r"((a)[1]), "r"((a)[2]), "r"((a)[3]),           \
                   "r"(bb0), "r"(bb1))

// ---------------------------------------------------------------------------
// Kernel 0: W prep (fp16 1-limb, SWZ layout, BK=64 chunks) + stm sniff.
// ---------------------------------------------------------------------------
__global__ void wprep_kernel(const float* __restrict__ ftw,
                             const unsigned char* __restrict__ stm) {
    const int t = threadIdx.x;
    if (blockIdx.x == NCH) {
        __shared__ int fFloat, fBool;
        if (t == 0) { fFloat = 0; fBool = 0; }
        __syncthreads();
        int lf = 0, lb = 0;
        for (int i = t; i < B_SZ; i += 256) {
            unsigned char v = stm[i];
            if (v == 0x80u || v == 0x3fu) lf = 1;
            else if (v != 0u && (i & 3) != 0) lb = 1;
        }
        if (lf) atomicOr(&fFloat, 1);
        if (lb) atomicOr(&fBool, 1);
        __syncthreads();
        if (t == 0) g_mode = fFloat ? 2 : (fBool ? 1 : 0);
        return;
    }
    const int c = blockIdx.x;
    const int n = t >> 1, lh = t & 1;
    const float* src = ftw + (size_t)n * F_SZ;
    unsigned char* dstC = g_wh + (size_t)c * WCHUNK;
#pragma unroll
    for (int s = 0; s < 4; s++) {
        const int kb = c * BK + s * 16 + lh * 8;
        float4 v0 = make_float4(0, 0, 0, 0), v1 = v0;
        if (kb + 4 <= F_SZ) v0 = *(const float4*)(src + kb);
        if (kb + 8 <= F_SZ) v1 = *(const float4*)(src + kb + 4);
        uint4 o;
        o.x = cvtH2(v0.x, v0.y);
        o.y = cvtH2(v0.z, v0.w);
        o.z = cvtH2(v1.x, v1.y);
        o.w = cvtH2(v1.z, v1.w);
        *(uint4*)(dstC + s * PLW + SWZ(n, lh)) = o;
    }
}

// ---------------------------------------------------------------------------
// Kernel 0c: per-neuron W rowsum (deterministic tree reduce). 128 blocks.
// ---------------------------------------------------------------------------
__global__ void wsum_kernel(const float* __restrict__ ftw) {
    __shared__ float red[256];
    const int n = blockIdx.x;
    float s = 0.0f;
    for (int k = threadIdx.x; k < F_SZ; k += 256) s += ftw[(size_t)n * F_SZ + k];
    red[threadIdx.x] = s;
    __syncthreads();
    for (int st = 128; st; st >>= 1) {
        if (threadIdx.x < st) red[threadIdx.x] += red[threadIdx.x + st];
        __syncthreads();
    }
    if (threadIdx.x == 0) g_wsum[n] = red[0];
}

// ---------------------------------------------------------------------------
// Kernel 1: fp16 1-term FT GEMM, centered A. M=64/CTA, grid (256,2)=512 CTAs.
// 256 thr, 8 warps (2m x 4n), warp tile 32x32, BK=64 as four k16 sub-steps,
// 2-stage pipeline, 48KB smem/CTA -> occ 3 (6 warps/SMSP), reg cap 84.
// ---------------------------------------------------------------------------
__global__ __launch_bounds__(256, 3)
void ft_mma_kernel(const float* __restrict__ white,
                   const float* __restrict__ black,
                   const float* __restrict__ ftb) {
    extern __shared__ char smc[];
    const int t = threadIdx.x;
    const int lane = t & 31, wid = t >> 5;
    const int wm = wid >> 2, wn = wid & 3;
    const int color = blockIdx.y;
    const int row0 = blockIdx.x * 64;
    const float* __restrict__ A = color ? black : white;
    const uint32_t base = smem_u32(smc);

    // A loader: ss = t>>7 selects sub-step pair {ss, ss+2}; 2 threads per row.
    const int ss = t >> 7;
    const int lrow = (t & 127) >> 1, lh = t & 1;
    const float* aRow = A + (size_t)(row0 + lrow) * F_SZ;
    const uint32_t aDst = SWZ(lrow, lh);
    const unsigned char* wSrc = g_wh + t * 16;

    float4 aq[4];   // pass0: aq[0..1], pass1: aq[2..3]

    auto ldA2 = [&](int ch) {
#pragma unroll
        for (int pass = 0; pass < 2; pass++) {
            const int kb = ch * BK + (ss + pass * 2) * 16 + lh * 8;
            aq[pass * 2 + 0] = (kb + 4 <= F_SZ) ? *(const float4*)(aRow + kb)
                                                : make_float4(0, 0, 0, 0);
            aq[pass * 2 + 1] = (kb + 8 <= F_SZ) ? *(const float4*)(aRow + kb + 4)
                                                : make_float4(0, 0, 0, 0);
        }
    };
    auto stsA = [&](int stg, int pass) {
        const float4 q0 = aq[pass * 2 + 0], q1 = aq[pass * 2 + 1];
        uint4 v;
        v.x = cvtH2(q0.x - 0.5f, q0.y - 0.5f);
        v.y = cvtH2(q0.z - 0.5f, q0.w - 0.5f);
        v.z = cvtH2(q1.x - 0.5f, q1.y - 0.5f);
        v.w = cvtH2(q1.z - 0.5f, q1.w - 0.5f);
        *(uint4*)(smc + stg * STG_SZ + (ss + pass * 2) * PLA + aDst) = v;
    };
    auto cpW = [&](int ch, int stg) {
        const uint32_t db = base + stg * STG_SZ + W_OFF + (uint32_t)(t * 16);
        const unsigned char* s = wSrc + (size_t)ch * WCHUNK;
#pragma unroll
        for (int p = 0; p < 4; p++)
            asm volatile("cp.async.cg.shared.global [%0], [%1], 16;"
                         :: "r"(db + p * PLW), "l"(s + p * PLW) : "memory");
    };

    // ldmatrix lane offsets
    const uint32_t offA = SWZ(wm * 32 + (lane & 15), lane >> 4);
    const uint32_t offB = SWZ(wn * 32 + ((lane >> 4) << 3) + (lane & 7), (lane >> 3) & 1);

    float acc[2][4][4];
#pragma unroll
    for (int i = 0; i < 2; i++)
#pragma unroll
        for (int j = 0; j < 4; j++)
#pragma unroll
            for (int q = 0; q < 4; q++) acc[i][j][q] = 0.0f;

    // ---- prologue: chunk 0 -> stage 0
    cpW(0, 0);
    asm volatile("cp.async.commit_group;" ::: "memory");
    ldA2(0);
    stsA(0, 0);
    stsA(0, 1);
    asm volatile("cp.async.wait_group 0;" ::: "memory");
    __syncthreads();

    for (int c = 0; c < NCH; ++c) {
        const int cur = c & 1, nxt = cur ^ 1;
        const bool more = (c + 1) < NCH;

        if (more) { ldA2(c + 1); cpW(c + 1, nxt); }
        asm volatile("cp.async.commit_group;" ::: "memory");

        const uint32_t sb = base + cur * STG_SZ;
#pragma unroll
        for (int s = 0; s < 4; s++) {
            const uint32_t aPl = sb + s * PLA;
            const uint32_t wPl = sb + W_OFF + s * PLW;
            uint32_t a[2][4], b[2][4];
            LDSM_X4(a[0], aPl + offA);
            LDSM_X4(a[1], aPl + offA + 512);
            LDSM_X4(b[0], wPl + offB);
            LDSM_X4(b[1], wPl + offB + 512);
#pragma unroll
            for (int mi = 0; mi < 2; mi++)
#pragma unroll
                for (int ni = 0; ni < 4; ni++) {
                    const int q = ni >> 1, r = (ni & 1) * 2;
                    MMA16816(acc[mi][ni], a[mi], b[q][r], b[q][r + 1]);
                }
            if (more && s == 1) stsA(nxt, 0);
            if (more && s == 3) stsA(nxt, 1);
        }

        asm volatile("cp.async.wait_group 0;" ::: "memory");
        __syncthreads();
    }

    // ---- epilogue: bias = ftb + 0.5*rowsum, screlu -> g_scratch
    float2 bias[4];
#pragma unroll
    for (int ni = 0; ni < 4; ni++) {
        const int n = wn * 32 + ni * 8 + (lane & 3) * 2;
        float2 b = *(const float2*)(ftb + n);
        float2 ws = *(const float2*)(g_wsum + n);
        bias[ni].x = b.x + 0.5f * ws.x;
        bias[ni].y = b.y + 0.5f * ws.y;
    }
#pragma unroll
    for (int mi = 0; mi < 2; mi++) {
#pragma unroll
        for (int hf = 0; hf < 2; hf++) {
            const int m = wm * 32 + mi * 16 + (lane >> 2) + hf * 8;
            float* dstRow = g_scratch + (size_t)(row0 + m) * 256 + color * 128;
#pragma unroll
            for (int ni = 0; ni < 4; ni++) {
                const int n = wn * 32 + ni * 8 + (lane & 3) * 2;
                float2 o;
                o.x = screlu(acc[mi][ni][hf * 2 + 0] + bias[ni].x);
                o.y = screlu(acc[mi][ni][hf * 2 + 1] + bias[ni].y);
                *(float2*)(dstRow + n) = o;
            }
        }
    }
}

// ---------------------------------------------------------------------------
// Kernel 2: tail MLP. 512 blocks x 8 warps x 4 rows/warp (R11-proven).
// ---------------------------------------------------------------------------
__global__ __launch_bounds__(256)
void tail_kernel(const unsigned char* __restrict__ stm,
                 const float* __restrict__ l1w, const float* __restrict__ l1b,
                 const float* __restrict__ l2w, const float* __restrict__ l2b,
                 const float* __restrict__ outw, const float* __restrict__ outb,
                 float* __restrict__ out) {
    __shared__ float l1w_s[32][260];
    __shared__ float xs[8][256];
    __shared__ float x1s[8][32];
    __shared__ float l2wT[32 * 32];
    __shared__ float l1b_s[32], l2b_s[32], outw_s[32];

    const int t = threadIdx.x;
    for (int idx = t; idx < 32 * 256; idx += 256) {
        int i = idx >> 8, k = idx & 255;
        l1w_s[i][k] = l1w[idx];
    }
    for (int idx = t; idx < 32 * 32; idx += 256) {
        int i = idx >> 5, j = idx & 31;
        l2wT[j * 32 + i] = l2w[idx];
    }
    if (t < 32) {
        l1b_s[t] = l1b[t];
        l2b_s[t] = l2b[t];
        outw_s[t] = outw[t];
    }
    __syncthreads();

    const int w = t >> 5;
    const int lane = t & 31;
    const int mode = g_mode;

#pragma unroll 1
    for (int rr = 0; rr < 4; ++rr) {
        const int r = blockIdx.x * 32 + w * 4 + rr;
        bool s;
        if (mode == 2)      s = (((const float*)(const void*)stm)[r] != 0.0f);
        else if (mode == 1) s = (stm[r] != 0u);
        else                s = (((const int*)(const void*)stm)[r] != 0);
        const int rot = s ? 128 : 0;

        const float* src = g_scratch + (size_t)r * 256;
#pragma unroll
        for (int p = 0; p < 2; p++) {
            const int fi = ((lane + 32 * p) * 4 + rot) & 255;
            *(float4*)&xs[w][(lane + 32 * p) * 4] = *(const float4*)(src + fi);
        }
        __syncwarp();

        float o1 = l1b_s[lane];
#pragma unroll 8
        for (int k4 = 0; k4 < 64; k4++) {
            float4 wv = *(const float4*)&l1w_s[lane][k4 * 4];
            float4 xv = *(const float4*)&xs[w][k4 * 4];
            o1 += wv.x * xv.x + wv.y * xv.y + wv.z * xv.z + wv.w * xv.w;
        }
        x1s[w][lane] = screlu(o1);
        __syncwarp();

        float o2 = l2b_s[lane];
#pragma unroll
        for (int j = 0; j < 32; j++)
            o2 += l2wT[j * 32 + lane] * x1s[w][j];

        float v = screlu(o2) * outw_s[lane];
#pragma unroll
        for (int off = 16; off; off >>= 1)
            v += __shfl_xor_sync(0xffffffffu, v, off);
        if (lane == 0) out[r] = v + outb[0];
        __syncwarp();
    }
}

// ---------------------------------------------------------------------------
extern "C" void kernel_launch(void* const* d_in, const int* in_sizes, int n_in,
                              void* d_out, int out_size) {
    const float* white = (const float*)d_in[0];
    const float* black = (const float*)d_in[1];
    const unsigned char* stm = (const unsigned char*)d_in[2];
    const float* ftw  = (const float*)d_in[3];
    const float* ftb  = (const float*)d_in[4];
    const float* l1w  = (const float*)d_in[5];
    const float* l1b  = (const float*)d_in[6];
    const float* l2w  = (const float*)d_in[7];
    const float* l2b  = (const float*)d_in[8];
    const float* outw = (const float*)d_in[9];
    const float* outb = (const float*)d_in[10];
    float* out = (float*)d_out;

    wprep_kernel<<<NCH + 1, 256>>>(ftw, stm);
    wsum_kernel<<<128, 256>>>(ftw);
    ft_mma_kernel<<<dim3(B_SZ / 64, 2), 256, SMEM_DYN>>>(white, black, ftb);
    tail_kernel<<<B_SZ / 32, 256>>>(stm, l1w, l1b, l2w, l2b, outw, outb, out);
}

// round 17
// speedup vs baseline: 1.1366x; 1.1366x over previous
#include <cuda_runtime.h>
#include <cuda_fp16.h>
#include <cstdint>

#define B_SZ 16384
#define F_SZ 9000
#define BK   96
#define NCH  94              // ceil(9000/96); last chunk 72 valid k
#define NSUB 6               // k16 substeps per chunk
#define PL   4096            // sub-plane bytes: 128 rows x 32B (k16)
// stage layout: A_s0..A_s5 [24KB] | W_s0..W_s5 [24KB] = 48KB
#define W_OFF   24576
#define WCHUNK  24576        // W bytes per chunk in g_wh (6 sub-planes)
#define STG_SZ  49152
#define SMEM_DYN (2 * STG_SZ)   // 98304 B via cudaFuncSetAttribute (R14-proven)

#define TAIL_SMEM 74624      // tail kernel dynamic smem (see offsets below)

__device__ float g_scratch[B_SZ * 256];
__device__ int g_mode;
__device__ float g_wsum[128];
__device__ unsigned char g_wh[NCH * WCHUNK];   // per-chunk fp16 W sub-planes, SWZ layout

__device__ __forceinline__ float screlu(float x) {
    x = fminf(fmaxf(x, 0.0f), 1.0f);
    return x * x;
}

__device__ __forceinline__ uint32_t smem_u32(const void* p) {
    uint32_t a;
    asm("{ .reg .u64 t; cvta.to.shared.u64 t, %1; cvt.u32.u64 %0, t; }" : "=r"(a) : "l"(p));
    return a;
}

// XOR swizzle for 32B rows: row r, 16B-half h -> conflict-free ldmatrix/STS
#define SWZ(r, h) ((uint32_t)((r) * 32 + (((h) ^ (((r) >> 2) & 1)) << 4)))

__device__ __forceinline__ uint32_t h2u(__half2 h) {
    uint32_t u;
    *(__half2*)&u = h;
    return u;
}
__device__ __forceinline__ uint32_t cvtH2(float x0, float x1) {
    return h2u(__floats2half2_rn(x0, x1));
}

#define LDSM_X4(r, addr)                                                         \
    asm volatile("ldmatrix.sync.aligned.m8n8.x4.shared.b16 {%0,%1,%2,%3}, [%4];" \
                 : "=r"((r)[0]), "=r"((r)[1]), "=r"((r)[2]), "=r"((r)[3])        \
                 : "r"(addr))

#define MMA16816(c, a, bb0, bb1)                                                 \
    asm volatile("mma.sync.aligned.m16n8k16.row.col.f32.f16.f16.f32 "            \
                 "{%0,%1,%2,%3}, {%4,%5,%6,%7}, {%8,%9}, {%0,%1,%2,%3};"         \
                 : "+f"((c)[0]), "+f"((c)[1]), "+f"((c)[2]), "+f"((c)[3])        \
                 : "r"((a)[0]), "r"((a)[1]), "r"((a)[2]), "r"((a)[3]),           \
                   "r"(bb0), "r"(bb1))

// ---------------------------------------------------------------------------
// Kernel 0: W prep (fp16 1-limb, SWZ layout, BK=96 chunks) + stm sniff.
// ---------------------------------------------------------------------------
__global__ void wprep_kernel(const float* __restrict__ ftw,
                             const unsigned char* __restrict__ stm) {
    const int t = threadIdx.x;
    if (blockIdx.x == NCH) {
        __shared__ int fFloat, fBool;
        if (t == 0) { fFloat = 0; fBool = 0; }
        __syncthreads();
        int lf = 0, lb = 0;
        for (int i = t; i < B_SZ; i += 256) {
            unsigned char v = stm[i];
            if (v == 0x80u || v == 0x3fu) lf = 1;
            else if (v != 0u && (i & 3) != 0) lb = 1;
        }
        if (lf) atomicOr(&fFloat, 1);
        if (lb) atomicOr(&fBool, 1);
        __syncthreads();
        if (t == 0) g_mode = fFloat ? 2 : (fBool ? 1 : 0);
        return;
    }
    const int c = blockIdx.x;
    const int n = t >> 1, lh = t & 1;
    const float* src = ftw + (size_t)n * F_SZ;
    unsigned char* dstC = g_wh + (size_t)c * WCHUNK;
#pragma unroll
    for (int s = 0; s < NSUB; s++) {
        const int kb = c * BK + s * 16 + lh * 8;
        float4 v0 = make_float4(0, 0, 0, 0), v1 = v0;
        if (kb + 4 <= F_SZ) v0 = *(const float4*)(src + kb);
        if (kb + 8 <= F_SZ) v1 = *(const float4*)(src + kb + 4);
        uint4 o;
        o.x = cvtH2(v0.x, v0.y);
        o.y = cvtH2(v0.z, v0.w);
        o.z = cvtH2(v1.x, v1.y);
        o.w = cvtH2(v1.z, v1.w);
        *(uint4*)(dstC + s * PL + SWZ(n, lh)) = o;
    }
}

// ---------------------------------------------------------------------------
// Kernel 0c: per-neuron W rowsum (deterministic tree reduce). 128 blocks.
// ---------------------------------------------------------------------------
__global__ void wsum_kernel(const float* __restrict__ ftw) {
    __shared__ float red[256];
    const int n = blockIdx.x;
    float s = 0.0f;
    for (int k = threadIdx.x; k < F_SZ; k += 256) s += ftw[(size_t)n * F_SZ + k];
    red[threadIdx.x] = s;
    __syncthreads();
    for (int st = 128; st; st >>= 1) {
        if (threadIdx.x < st) red[threadIdx.x] += red[threadIdx.x + st];
        __syncthreads();
    }
    if (threadIdx.x == 0) g_wsum[n] = red[0];
}

// ---------------------------------------------------------------------------
// Kernel 1: fp16 1-term FT GEMM, centered A. M=128/CTA, 256 thr, 8 warps
// (2m x 4n, 64x32 tiles), BK=96 as six k16 sub-steps with b-frag double
// buffering, 2-stage cp.async pipeline, 96KB dyn smem, occ 2.
// ---------------------------------------------------------------------------
__global__ __launch_bounds__(256, 2)
void ft_mma_kernel(const float* __restrict__ white,
                   const float* __restrict__ black,
                   const float* __restrict__ ftb) {
    extern __shared__ char smc[];
    const int t = threadIdx.x;
    const int lane = t & 31, wid = t >> 5;
    const int wm = wid >> 2, wn = wid & 3;
    const int color = blockIdx.y;
    const int row0 = blockIdx.x * 128;
    const float* __restrict__ A = color ? black : white;
    const uint32_t base = smem_u32(smc);

    // loader: thread pair per row, 16B-half lh = t&1
    const int lrow = t >> 1, lh = t & 1;
    const float* aRow = A + (size_t)(row0 + lrow) * F_SZ;
    const uint32_t aDst = SWZ(lrow, lh);
    const unsigned char* wSrc = g_wh + t * 16;

    float4 aq[2];

    auto ldA = [&](int ch, int s) {
        const int kb = ch * BK + s * 16 + lh * 8;
        aq[0] = (kb + 4 <= F_SZ) ? *(const float4*)(aRow + kb) : make_float4(0, 0, 0, 0);
        aq[1] = (kb + 8 <= F_SZ) ? *(const float4*)(aRow + kb + 4) : make_float4(0, 0, 0, 0);
    };
    auto stsA = [&](int stg, int s) {
        uint4 v;
        v.x = cvtH2(aq[0].x - 0.5f, aq[0].y - 0.5f);
        v.y = cvtH2(aq[0].z - 0.5f, aq[0].w - 0.5f);
        v.z = cvtH2(aq[1].x - 0.5f, aq[1].y - 0.5f);
        v.w = cvtH2(aq[1].z - 0.5f, aq[1].w - 0.5f);
        *(uint4*)(smc + stg * STG_SZ + s * PL + aDst) = v;
    };
    auto cpW = [&](int ch, int stg) {
        const uint32_t db = base + stg * STG_SZ + W_OFF + (uint32_t)(t * 16);
        const unsigned char* s = wSrc + (size_t)ch * WCHUNK;
#pragma unroll
        for (int p = 0; p < NSUB; p++)
            asm volatile("cp.async.cg.shared.global [%0], [%1], 16;"
                         :: "r"(db + p * PL), "l"(s + p * PL) : "memory");
    };

    // ldmatrix lane offsets
    const uint32_t offA = SWZ(wm * 64 + (lane & 15), lane >> 4);
    const uint32_t offB = SWZ(wn * 32 + ((lane >> 4) << 3) + (lane & 7), (lane >> 3) & 1);

    float acc[4][4][4];
#pragma unroll
    for (int i = 0; i < 4; i++)
#pragma unroll
        for (int j = 0; j < 4; j++)
#pragma unroll
            for (int q = 0; q < 4; q++) acc[i][j][q] = 0.0f;

    // ---- prologue: chunk 0 -> stage 0
    cpW(0, 0);
    asm volatile("cp.async.commit_group;" ::: "memory");
#pragma unroll
    for (int s = 0; s < NSUB; s++) { ldA(0, s); stsA(0, s); }
    asm volatile("cp.async.wait_group 0;" ::: "memory");
    __syncthreads();

    for (int c = 0; c < NCH; ++c) {
        const int cur = c & 1, nxt = cur ^ 1;
        const bool more = (c + 1) < NCH;

        if (more) { ldA(c + 1, 0); cpW(c + 1, nxt); }
        asm volatile("cp.async.commit_group;" ::: "memory");

        const uint32_t sb = base + cur * STG_SZ;
        const uint32_t wb = sb + W_OFF;
        uint32_t b[2][2][4];
        // preload b frags for substep 0
        LDSM_X4(b[0][0], wb + offB);
        LDSM_X4(b[0][1], wb + offB + 512);
#pragma unroll
        for (int s = 0; s < NSUB; s++) {
            const int bc = s & 1;
            uint32_t a[4][4];
#pragma unroll
            for (int mi = 0; mi < 4; mi++) LDSM_X4(a[mi], sb + s * PL + offA + mi * 512);
            if (s + 1 < NSUB) {
                LDSM_X4(b[bc ^ 1][0], wb + (s + 1) * PL + offB);
                LDSM_X4(b[bc ^ 1][1], wb + (s + 1) * PL + offB + 512);
            }
#pragma unroll
            for (int mi = 0; mi < 4; mi++)
#pragma unroll
                for (int ni = 0; ni < 4; ni++) {
                    const int q = ni >> 1, r = (ni & 1) * 2;
                    MMA16816(acc[mi][ni], a[mi], b[bc][q][r], b[bc][q][r + 1]);
                }
            // spread next-chunk A prep across the substeps
            if (more && s < NSUB - 1) { stsA(nxt, s); ldA(c + 1, s + 1); }
        }
        if (more) stsA(nxt, NSUB - 1);

        asm volatile("cp.async.wait_group 0;" ::: "memory");
        __syncthreads();
    }

    // ---- epilogue: bias = ftb + 0.5*rowsum, screlu -> g_scratch
    float2 bias[4];
#pragma unroll
    for (int ni = 0; ni < 4; ni++) {
        const int n = wn * 32 + ni * 8 + (lane & 3) * 2;
        float2 b2 = *(const float2*)(ftb + n);
        float2 ws = *(const float2*)(g_wsum + n);
        bias[ni].x = b2.x + 0.5f * ws.x;
        bias[ni].y = b2.y + 0.5f * ws.y;
    }
#pragma unroll
    for (int mi = 0; mi < 4; mi++) {
#pragma unroll
        for (int hf = 0; hf < 2; hf++) {
            const int m = wm * 64 + mi * 16 + (lane >> 2) + hf * 8;
            float* dstRow = g_scratch + (size_t)(row0 + m) * 256 + color * 128;
#pragma unroll
            for (int ni = 0; ni < 4; ni++) {
                const int n = wn * 32 + ni * 8 + (lane & 3) * 2;
                float2 o;
                o.x = screlu(acc[mi][ni][hf * 2 + 0] + bias[ni].x);
                o.y = screlu(acc[mi][ni][hf * 2 + 1] + bias[ni].y);
                *(float2*)(dstRow + n) = o;
            }
        }
    }
}

// ---------------------------------------------------------------------------
// Kernel 2: tail MLP. 256 blocks x 8 warps x 8 rows (2 quads of 4).
// 4 rows processed jointly -> l1 weight LDS shared across rows (traffic /4).
// Dynamic smem layout (floats):
//   l1w_s  @0      [32][260]  8320
//   xs     @8320   [8][4][256] 8192
//   x1s    @16512  [8][4][32] 1024
//   l2wT   @17536  [32*32]    1024
//   l1b_s  @18560  [32], l2b_s @18592 [32], outw_s @18624 [32]
// total 18656 floats = 74624 B (attribute).
// ---------------------------------------------------------------------------
__global__ __launch_bounds__(256)
void tail_kernel(const unsigned char* __restrict__ stm,
                 const float* __restrict__ l1w, const float* __restrict__ l1b,
                 const float* __restrict__ l2w, const float* __restrict__ l2b,
                 const float* __restrict__ outw, const float* __restrict__ outb,
                 float* __restrict__ out) {
    extern __shared__ float tsm[];
    float* l1w_s = tsm;              // stride 260
    float* xs    = tsm + 8320;       // [w][rr][k]
    float* x1s   = tsm + 16512;      // [w][rr][i]
    float* l2wT  = tsm + 17536;
    float* l1b_s = tsm + 18560;
    float* l2b_s = tsm + 18592;
    float* outw_s = tsm + 18624;

    const int t = threadIdx.x;
    for (int idx = t; idx < 32 * 256; idx += 256) {
        int i = idx >> 8, k = idx & 255;
        l1w_s[i * 260 + k] = l1w[idx];
    }
    for (int idx = t; idx < 32 * 32; idx += 256) {
        int i = idx >> 5, j = idx & 31;
        l2wT[j * 32 + i] = l2w[idx];
    }
    if (t < 32) {
        l1b_s[t] = l1b[t];
        l2b_s[t] = l2b[t];
        outw_s[t] = outw[t];
    }
    __syncthreads();

    const int w = t >> 5;
    const int lane = t & 31;
    const int mode = g_mode;

#pragma unroll 1
    for (int quad = 0; quad < 2; ++quad) {
        const int rbase = blockIdx.x * 64 + w * 8 + quad * 4;

        // stage xs for 4 rows (rotation applied at load)
#pragma unroll
        for (int rr = 0; rr < 4; ++rr) {
            const int r = rbase + rr;
            bool s;
            if (mode == 2)      s = (((const float*)(const void*)stm)[r] != 0.0f);
            else if (mode == 1) s = (stm[r] != 0u);
            else                s = (((const int*)(const void*)stm)[r] != 0);
            const int rot = s ? 128 : 0;
            const float* src = g_scratch + (size_t)r * 256;
#pragma unroll
            for (int p = 0; p < 2; p++) {
                const int fi = ((lane + 32 * p) * 4 + rot) & 255;
                *(float4*)&xs[(w * 4 + rr) * 256 + (lane + 32 * p) * 4] =
                    *(const float4*)(src + fi);
            }
        }
        __syncwarp();

        // layer 1: lane = neuron; 4 rows share each weight read
        float o1[4];
#pragma unroll
        for (int rr = 0; rr < 4; ++rr) o1[rr] = l1b_s[lane];
#pragma unroll 4
        for (int k4 = 0; k4 < 64; k4++) {
            float4 wv = *(const float4*)&l1w_s[lane * 260 + k4 * 4];
#pragma unroll
            for (int rr = 0; rr < 4; ++rr) {
                float4 xv = *(const float4*)&xs[(w * 4 + rr) * 256 + k4 * 4];
                o1[rr] += wv.x * xv.x + wv.y * xv.y + wv.z * xv.z + wv.w * xv.w;
            }
        }
#pragma unroll
        for (int rr = 0; rr < 4; ++rr)
            x1s[(w * 4 + rr) * 32 + lane] = screlu(o1[rr]);
        __syncwarp();

        // layer 2 + output
        float o2[4];
#pragma unroll
        for (int rr = 0; rr < 4; ++rr) o2[rr] = l2b_s[lane];
#pragma unroll
        for (int j = 0; j < 32; j++) {
            float lv = l2wT[j * 32 + lane];
#pragma unroll
            for (int rr = 0; rr < 4; ++rr)
                o2[rr] += lv * x1s[(w * 4 + rr) * 32 + j];
        }
#pragma unroll
        for (int rr = 0; rr < 4; ++rr) {
            float v = screlu(o2[rr]) * outw_s[lane];
#pragma unroll
            for (int off = 16; off; off >>= 1)
                v += __shfl_xor_sync(0xffffffffu, v, off);
            if (lane == 0) out[rbase + rr] = v + outb[0];
        }
        __syncwarp();
    }
}

// ---------------------------------------------------------------------------
extern "C" void kernel_launch(void* const* d_in, const int* in_sizes, int n_in,
                              void* d_out, int out_size) {
    const float* white = (const float*)d_in[0];
    const float* black = (const float*)d_in[1];
    const unsigned char* stm = (const unsigned char*)d_in[2];
    const float* ftw  = (const float*)d_in[3];
    const float* ftb  = (const float*)d_in[4];
    const float* l1w  = (const float*)d_in[5];
    const float* l1b  = (const float*)d_in[6];
    const float* l2w  = (const float*)d_in[7];
    const float* l2b  = (const float*)d_in[8];
    const float* outw = (const float*)d_in[9];
    const float* outb = (const float*)d_in[10];
    float* out = (float*)d_out;

    static int smem_set = 0;
    if (!smem_set) {
        cudaFuncSetAttribute(ft_mma_kernel,
                             cudaFuncAttributeMaxDynamicSharedMemorySize, SMEM_DYN);
        cudaFuncSetAttribute(tail_kernel,
                             cudaFuncAttributeMaxDynamicSharedMemorySize, TAIL_SMEM);
        smem_set = 1;
    }

    wprep_kernel<<<NCH + 1, 256>>>(ftw, stm);
    wsum_kernel<<<128, 256>>>(ftw);
    ft_mma_kernel<<<dim3(B_SZ / 128, 2), 256, SMEM_DYN>>>(white, black, ftb);
    tail_kernel<<<B_SZ / 64, 256, TAIL_SMEM>>>(stm, l1w, l1b, l2w, l2b, outw, outb, out);
}